// round 13
// baseline (speedup 1.0000x reference)
#include <cuda_runtime.h>
#include <cuda_fp16.h>
#include <cstdint>
#include <math.h>

#define B_  2
#define N_  2048
#define NC_ 128
#define D_  2048
#define H_  16
#define DH_ 128
#define L_  (N_ + NC_)     // 2176
#define D3_ (3 * D_)       // 6144

// ---------------- scratch (device globals; no allocations allowed) ----------
__device__ float  g_Q[(size_t)B_ * H_ * L_ * DH_];    // fp32 pre-norm
__device__ float  g_K[(size_t)B_ * H_ * L_ * DH_];
__device__ __half g_Qh[(size_t)B_ * H_ * L_ * DH_];   // fp16 post-norm/rope (Q pre-scaled by log2e/sqrt(dh))
__device__ __half g_Kh[(size_t)B_ * H_ * L_ * DH_];
__device__ __half g_Vt[(size_t)B_ * H_ * DH_ * L_];   // fp16 (b,h,dh,l)
__device__ __half g_Oh[(size_t)B_ * N_ * D_];
__device__ __half g_hx[(size_t)B_ * N_ * D_];
__device__ __half g_hc[(size_t)B_ * NC_ * D_];
__device__ __half g_hwqkv[(size_t)D3_ * D_];
__device__ __half g_hwcq[(size_t)D3_ * D_];
__device__ __half g_hwo[(size_t)D_ * D_];
__device__ float2 g_rope[(size_t)L_ * 64];

__device__ __forceinline__ uint32_t smem_u32(const void* p) {
    uint32_t a;
    asm("{ .reg .u64 t; cvta.to.shared.u64 t, %1; cvt.u32.u64 %0, t; }" : "=r"(a) : "l"(p));
    return a;
}
__device__ __forceinline__ void cp16(uint32_t saddr, const void* gaddr) {
    asm volatile("cp.async.cg.shared.global [%0], [%1], 16;" :: "r"(saddr), "l"(gaddr));
}
#define CP_COMMIT() asm volatile("cp.async.commit_group;" ::: "memory")
#define CP_WAIT1()  asm volatile("cp.async.wait_group 1;" ::: "memory")

__device__ __forceinline__ void mma_f16(float* d, const uint32_t* a, const uint32_t* b) {
    asm volatile(
        "mma.sync.aligned.m16n8k16.row.col.f32.f16.f16.f32 "
        "{%0,%1,%2,%3},{%4,%5,%6,%7},{%8,%9},{%0,%1,%2,%3};"
        : "+f"(d[0]), "+f"(d[1]), "+f"(d[2]), "+f"(d[3])
        : "r"(a[0]), "r"(a[1]), "r"(a[2]), "r"(a[3]), "r"(b[0]), "r"(b[1]));
}
__device__ __forceinline__ void ldmx4(uint32_t* r, uint32_t addr) {
    asm volatile("ldmatrix.sync.aligned.m8n8.x4.shared.b16 {%0,%1,%2,%3}, [%4];"
        : "=r"(r[0]), "=r"(r[1]), "=r"(r[2]), "=r"(r[3]) : "r"(addr));
}
__device__ __forceinline__ uint32_t packh2(float a, float b) {
    __half2 h = __floats2half2_rn(a, b);
    return *(uint32_t*)&h;
}

// ---------------- fused fp32 -> fp16 conversion prepass ----------------------
#define NX8  ((B_ * N_ * D_) / 8)
#define NC8  ((B_ * NC_ * D_) / 8)
#define NW8  ((D3_ * D_) / 8)
#define NO8  ((D_ * D_) / 8)
#define NT8  (NX8 + NC8 + 2 * NW8 + NO8)

__global__ void cvt_all(const float* __restrict__ x, const float* __restrict__ c,
                        const float* __restrict__ wqkv, const float* __restrict__ wcq,
                        const float* __restrict__ wo)
{
    for (int i = blockIdx.x * blockDim.x + threadIdx.x; i < NT8; i += gridDim.x * blockDim.x) {
        const float* src; __half* dst; int j = i;
        if (j < NX8)                { src = x;    dst = g_hx; }
        else if ((j -= NX8) < NC8)  { src = c;    dst = g_hc; }
        else if ((j -= NC8) < NW8)  { src = wqkv; dst = g_hwqkv; }
        else if ((j -= NW8) < NW8)  { src = wcq;  dst = g_hwcq; }
        else { j -= NW8;              src = wo;   dst = g_hwo; }
        float4 a = *(const float4*)(src + (size_t)j * 8);
        float4 b = *(const float4*)(src + (size_t)j * 8 + 4);
        uint4 o;
        o.x = packh2(a.x, a.y); o.y = packh2(a.z, a.w);
        o.z = packh2(b.x, b.y); o.w = packh2(b.z, b.w);
        *(uint4*)(dst + (size_t)j * 8) = o;
    }
}

// ---------------- RoPE table --------------------------------------------------
__global__ void rope_table_k()
{
    const int l = blockIdx.x, i = threadIdx.x;
    const float invf = (float)(1.0 / pow(10000.0, (double)i / 64.0));
    const float ang  = (float)l * invf;
    g_rope[l * 64 + i] = make_float2((float)cos((double)ang), (float)sin((double)ang));
}

// ================= fp16 mma GEMM: 4 warps, 64x64 warp tiles =================
// 128x128 CTA tile, KSLAB=32, 3-stage cp.async, 2 CTAs/SM.
// MODE 0: fused self+cross QKV; MODE 2: out-proj + bias.
#define KSLAB  32
#define APADH  40
#define STG_H  (128 * APADH)
#define GEMM_SMEM (3 * 2 * STG_H * 2)      // 61440

template <int MODE>
__global__ __launch_bounds__(128, 2)
void gemm_h(const __half* __restrict__ A0, const __half* __restrict__ A1,
            const __half* __restrict__ W0, const __half* __restrict__ W1,
            const float* __restrict__ bias, float* __restrict__ out)
{
    constexpr int K = D_;
    constexpr int NS = K / KSLAB;
    extern __shared__ __half smh[];

    const int t = threadIdx.x;
    const int wid = t >> 5, lane = t & 31;
    const int g = lane >> 2, tig = lane & 3;
    const int wm = (wid >> 1) * 64;        // warp m offset (0/64)
    const int wn = (wid & 1) * 64;         // warp n offset (0/64)
    const int n0 = blockIdx.x * 128;

    const bool cross = (MODE == 0) && (blockIdx.y >= 32);
    const int m0 = (MODE == 0) ? (cross ? (blockIdx.y - 32) * 128 : blockIdx.y * 128)
                               : blockIdx.y * 128;
    const __half* A = (MODE == 0) ? (cross ? A1 : A0) : A0;
    const __half* W = (MODE == 0) ? (cross ? W1 : W0) : W0;

    const int a_ro = (lane & 7) + ((lane >> 3) & 1) * 8;
    const int a_co = ((lane >> 4) & 1) * 8;
    const int b_ro = (lane & 7) + ((lane >> 4) & 1) * 8;
    const int b_co = ((lane >> 3) & 1) * 8;

    // cp.async: thread t owns row t (4 chunks of 8 halves) of A and of B
    const __half* aRow = A + (size_t)(m0 + t) * K;
    const __half* bRow = W + (size_t)(n0 + t) * K;
    const uint32_t sbase = smem_u32(smh);

    float acc[4][8][4];
#pragma unroll
    for (int mi = 0; mi < 4; mi++)
#pragma unroll
        for (int ni = 0; ni < 8; ni++)
#pragma unroll
            for (int r = 0; r < 4; r++) acc[mi][ni][r] = 0.0f;

    auto issue = [&](int slab) {
        const int s = slab % 3;
        const uint32_t as = sbase + (uint32_t)(s * 2 * STG_H) * 2;
        const uint32_t bs = as + (uint32_t)STG_H * 2;
        const int ko = slab * KSLAB;
        const uint32_t soff = (uint32_t)(t * APADH) * 2;
#pragma unroll
        for (int c8 = 0; c8 < 4; c8++) {
            cp16(as + soff + c8 * 16, aRow + ko + c8 * 8);
            cp16(bs + soff + c8 * 16, bRow + ko + c8 * 8);
        }
    };

    issue(0); CP_COMMIT();
    issue(1); CP_COMMIT();

    for (int kt = 0; kt < NS; kt++) {
        CP_WAIT1();
        __syncthreads();
        if (kt + 2 < NS) issue(kt + 2);
        CP_COMMIT();

        const uint32_t as_u = sbase + (uint32_t)((kt % 3) * 2 * STG_H) * 2;
        const uint32_t bs_u = as_u + (uint32_t)STG_H * 2;
#pragma unroll
        for (int ks = 0; ks < 2; ks++) {
            const int kb = ks * 16;
            uint32_t bf[8][2];
#pragma unroll
            for (int np = 0; np < 4; np++) {
                uint32_t r[4];
                ldmx4(r, bs_u + (uint32_t)((wn + np * 16 + b_ro) * APADH + kb + b_co) * 2);
                bf[2 * np][0] = r[0]; bf[2 * np][1] = r[1];
                bf[2 * np + 1][0] = r[2]; bf[2 * np + 1][1] = r[3];
            }
#pragma unroll
            for (int mi = 0; mi < 4; mi++) {
                uint32_t af[4];
                ldmx4(af, as_u + (uint32_t)((wm + mi * 16 + a_ro) * APADH + kb + a_co) * 2);
#pragma unroll
                for (int ni = 0; ni < 8; ni++)
                    mma_f16(acc[mi][ni], af, bf[ni]);
            }
        }
    }

    if (MODE == 0) {
        const int part = n0 >> 11;
        const int hh   = (n0 & 2047) >> 7;
#pragma unroll
        for (int mi = 0; mi < 4; mi++) {
#pragma unroll
            for (int hi = 0; hi < 2; hi++) {
                const int m = m0 + wm + mi * 16 + g + hi * 8;
                int b, l;
                if (!cross) { b = m >> 11; l = m & 2047; }
                else        { b = m >> 7;  l = N_ + (m & 127); }
                if (part < 2) {
                    float* dst = (part == 0) ? g_Q : g_K;
                    float* rowp = dst + ((size_t)(b * H_ + hh) * L_ + l) * DH_;
#pragma unroll
                    for (int ni = 0; ni < 8; ni++) {
                        const int dh = wn + ni * 8 + 2 * tig;
                        *(float2*)(rowp + dh) = make_float2(acc[mi][ni][hi * 2], acc[mi][ni][hi * 2 + 1]);
                    }
                } else {
                    __half* vb = g_Vt + (size_t)(b * H_ + hh) * DH_ * L_;
#pragma unroll
                    for (int ni = 0; ni < 8; ni++) {
                        const int dh = wn + ni * 8 + 2 * tig;
                        vb[(size_t)dh * L_ + l]       = __float2half(acc[mi][ni][hi * 2]);
                        vb[(size_t)(dh + 1) * L_ + l] = __float2half(acc[mi][ni][hi * 2 + 1]);
                    }
                }
            }
        }
    } else {
#pragma unroll
        for (int mi = 0; mi < 4; mi++) {
#pragma unroll
            for (int hi = 0; hi < 2; hi++) {
                const int m = m0 + wm + mi * 16 + g + hi * 8;
                float* op = out + (size_t)m * D_;
#pragma unroll
                for (int ni = 0; ni < 8; ni++) {
                    const int n = n0 + wn + ni * 8 + 2 * tig;
                    *(float2*)(op + n) = make_float2(acc[mi][ni][hi * 2] + bias[n],
                                                     acc[mi][ni][hi * 2 + 1] + bias[n + 1]);
                }
            }
        }
    }
}

// ---------------- L2-norm + scale + RoPE; warp per row, no smem --------------
__global__ __launch_bounds__(256)
void normrope_k(const float* __restrict__ scale, const float* __restrict__ cscale)
{
    const int wid = threadIdx.x >> 5, lane = threadIdx.x & 31;
    const int rg = blockIdx.x * 8 + wid;
    const int b = rg / (H_ * L_);
    const int rem = rg - b * (H_ * L_);
    const int h = rem / L_;
    const int l = rem - h * L_;

    const size_t rbase = (size_t)rg * DH_;
    const int c0 = lane * 4;
    const float* scp = (l < N_) ? scale : cscale;
    const float4 sc4 = *(const float4*)(scp + h * DH_ + c0);
    const float kmul = 45.25483399593904f;                              // sqrt(2048)
    const float qmul = kmul * 0.08838834764831845f * 1.44269504088896f; // /sqrt(128)*log2(e)

    const int i0 = c0 & 63;
    float cs[4], sn[4];
#pragma unroll
    for (int j = 0; j < 4; j++) {
        float2 rp = g_rope[l * 64 + i0 + j];
        cs[j] = rp.x; sn[j] = rp.y;
    }
    const bool lo = (lane < 16);

#pragma unroll
    for (int which = 0; which < 2; which++) {
        const float* ptr = ((which == 0) ? g_Q : g_K) + rbase;
        __half* hout = ((which == 0) ? g_Qh : g_Kh) + rbase;
        const float mul = (which == 0) ? qmul : kmul;

        float4 v4 = *(const float4*)(ptr + c0);
        float v[4] = {v4.x, v4.y, v4.z, v4.w};
        float ss = v[0] * v[0] + v[1] * v[1] + v[2] * v[2] + v[3] * v[3];
#pragma unroll
        for (int o = 16; o > 0; o >>= 1) ss += __shfl_xor_sync(0xffffffffu, ss, o);
        const float inv = 1.0f / fmaxf(sqrtf(ss), 1e-12f);

        float w[4];
        w[0] = v[0] * inv * sc4.x; w[1] = v[1] * inv * sc4.y;
        w[2] = v[2] * inv * sc4.z; w[3] = v[3] * inv * sc4.w;
        w[0] *= mul; w[1] *= mul; w[2] *= mul; w[3] *= mul;

        float o[4];
#pragma unroll
        for (int j = 0; j < 4; j++) {
            float p = __shfl_xor_sync(0xffffffffu, w[j], 16);
            o[j] = lo ? (w[j] * cs[j] - p * sn[j]) : (p * sn[j] + w[j] * cs[j]);
        }
        uint2 st; st.x = packh2(o[0], o[1]); st.y = packh2(o[2], o[3]);
        *(uint2*)(hout + c0) = st;
    }
}

// ---------------- flash attention: 4 warps, 64 q, register-resident P --------
#define SKH  136
#define SVTH 72
#define OFF_K   0
#define OFF_VT  (2 * 64 * SKH)
#define ATT_HALVES (OFF_VT + 2 * 128 * SVTH)
#define ATT_SMEM (ATT_HALVES * 2)        // 71680 B

__global__ __launch_bounds__(128)
void attn_h()
{
    extern __shared__ __half smh[];
    const int qt = blockIdx.x, h = blockIdx.y, b = blockIdx.z;
    const int t = threadIdx.x;
    const int wid = t >> 5, lane = t & 31;
    const int g = lane >> 2, tig = lane & 3;
    const int q0 = qt * 64, wrow = wid * 16;
    const size_t base = (size_t)(b * H_ + h) * L_ * DH_;
    const uint32_t sbase = smem_u32(smh);

    const int a_ro = (lane & 7) + ((lane >> 3) & 1) * 8;
    const int a_co = ((lane >> 4) & 1) * 8;
    const int b_ro = (lane & 7) + ((lane >> 4) & 1) * 8;
    const int b_co = ((lane >> 3) & 1) * 8;

    // ---- stage 64-row Q tile, load fragments
    {
        const __half* gq = g_Qh + base + (size_t)q0 * DH_;
#pragma unroll
        for (int ii = 0; ii < 8; ii++) {
            int idx = ii * 128 + t;
            int r = idx >> 4, c8 = (idx & 15) * 8;
            *(uint4*)(smh + r * SKH + c8) = *(const uint4*)(gq + (size_t)r * DH_ + c8);
        }
    }
    __syncthreads();
    uint32_t qf[8][4];
#pragma unroll
    for (int ks = 0; ks < 8; ks++)
        ldmx4(qf[ks], sbase + (uint32_t)((wrow + a_ro) * SKH + ks * 16 + a_co) * 2);
    __syncthreads();

    const __half* gk = g_Kh + base;
    const __half* gvt = g_Vt + (size_t)(b * H_ + h) * DH_ * L_;

    auto issue = [&](int kt) {
        const int bb = kt & 1;
        const int k0 = kt * 64;
#pragma unroll
        for (int ii = 0; ii < 8; ii++) {
            int idx = ii * 128 + t;
            int r = idx >> 4, c8 = (idx & 15) * 8;
            cp16(sbase + (uint32_t)(OFF_K + bb * 64 * SKH + r * SKH + c8) * 2,
                 gk + (size_t)(k0 + r) * DH_ + c8);
        }
#pragma unroll
        for (int ii = 0; ii < 8; ii++) {
            int idx = ii * 128 + t;
            int dh = idx >> 3, c8 = (idx & 7) * 8;
            cp16(sbase + (uint32_t)(OFF_VT + bb * 128 * SVTH + dh * SVTH + c8) * 2,
                 gvt + (size_t)dh * L_ + k0 + c8);
        }
    };

    float acc[16][4];
#pragma unroll
    for (int nt = 0; nt < 16; nt++)
#pragma unroll
        for (int r = 0; r < 4; r++) acc[nt][r] = 0.0f;
    float m0 = -INFINITY, m1 = -INFINITY, l0 = 0.0f, l1 = 0.0f;

    issue(0); CP_COMMIT();

    constexpr int NT = L_ / 64;   // 34
    for (int kt = 0; kt < NT; kt++) {
        __syncthreads();
        if (kt + 1 < NT) issue(kt + 1);
        CP_COMMIT();
        CP_WAIT1();
        __syncthreads();

        const uint32_t sK_u = sbase + (uint32_t)(OFF_K + (kt & 1) * 64 * SKH) * 2;
        const uint32_t sVt_u = sbase + (uint32_t)(OFF_VT + (kt & 1) * 128 * SVTH) * 2;

        // ---- S = Q K^T   (scores already in log2 domain via Q prescale)
        float sfr[8][4];
#pragma unroll
        for (int nt = 0; nt < 8; nt++)
#pragma unroll
            for (int r = 0; r < 4; r++) sfr[nt][r] = 0.0f;
#pragma unroll
        for (int ks = 0; ks < 8; ks++) {
            const int kb = ks * 16;
            uint32_t kf[8][2];
#pragma unroll
            for (int np = 0; np < 4; np++) {
                uint32_t r[4];
                ldmx4(r, sK_u + (uint32_t)((np * 16 + b_ro) * SKH + kb + b_co) * 2);
                kf[2 * np][0] = r[0]; kf[2 * np][1] = r[1];
                kf[2 * np + 1][0] = r[2]; kf[2 * np + 1][1] = r[3];
            }
#pragma unroll
            for (int nt = 0; nt < 8; nt++)
                mma_f16(sfr[nt], qf[ks], kf[nt]);
        }

        // ---- online softmax (base 2), P packed directly into mma A-fragments
        float mx0 = -INFINITY, mx1 = -INFINITY;
#pragma unroll
        for (int nt = 0; nt < 8; nt++) {
            mx0 = fmaxf(mx0, fmaxf(sfr[nt][0], sfr[nt][1]));
            mx1 = fmaxf(mx1, fmaxf(sfr[nt][2], sfr[nt][3]));
        }
        mx0 = fmaxf(mx0, __shfl_xor_sync(0xffffffffu, mx0, 1));
        mx0 = fmaxf(mx0, __shfl_xor_sync(0xffffffffu, mx0, 2));
        mx1 = fmaxf(mx1, __shfl_xor_sync(0xffffffffu, mx1, 1));
        mx1 = fmaxf(mx1, __shfl_xor_sync(0xffffffffu, mx1, 2));
        const float mn0 = fmaxf(m0, mx0), mn1 = fmaxf(m1, mx1);
        const float r0 = exp2f(m0 - mn0), r1 = exp2f(m1 - mn1);
        m0 = mn0; m1 = mn1;

        uint32_t pf[4][4];
        float s0 = 0.0f, s1 = 0.0f;
#pragma unroll
        for (int ks = 0; ks < 4; ks++) {
            const float p00 = exp2f(sfr[2 * ks][0] - mn0);
            const float p01 = exp2f(sfr[2 * ks][1] - mn0);
            const float p10 = exp2f(sfr[2 * ks][2] - mn1);
            const float p11 = exp2f(sfr[2 * ks][3] - mn1);
            const float q00 = exp2f(sfr[2 * ks + 1][0] - mn0);
            const float q01 = exp2f(sfr[2 * ks + 1][1] - mn0);
            const float q10 = exp2f(sfr[2 * ks + 1][2] - mn1);
            const float q11 = exp2f(sfr[2 * ks + 1][3] - mn1);
            s0 += p00 + p01 + q00 + q01;
            s1 += p10 + p11 + q10 + q11;
            pf[ks][0] = packh2(p00, p01);
            pf[ks][1] = packh2(p10, p11);
            pf[ks][2] = packh2(q00, q01);
            pf[ks][3] = packh2(q10, q11);
        }
        s0 += __shfl_xor_sync(0xffffffffu, s0, 1);
        s0 += __shfl_xor_sync(0xffffffffu, s0, 2);
        s1 += __shfl_xor_sync(0xffffffffu, s1, 1);
        s1 += __shfl_xor_sync(0xffffffffu, s1, 2);
        l0 = l0 * r0 + s0;
        l1 = l1 * r1 + s1;
#pragma unroll
        for (int nt = 0; nt < 16; nt++) {
            acc[nt][0] *= r0; acc[nt][1] *= r0;
            acc[nt][2] *= r1; acc[nt][3] *= r1;
        }

        // ---- PV: acc += P V
#pragma unroll
        for (int ks = 0; ks < 4; ks++) {
            const int kb = ks * 16;
#pragma unroll
            for (int np = 0; np < 8; np++) {
                uint32_t r[4];
                ldmx4(r, sVt_u + (uint32_t)((np * 16 + b_ro) * SVTH + kb + b_co) * 2);
                mma_f16(acc[2 * np], pf[ks], r);
                mma_f16(acc[2 * np + 1], pf[ks], r + 2);
            }
        }
    }

    // ---- epilogue (fp16 out)
    const float i0 = 1.0f / l0, i1 = 1.0f / l1;
    __half* o0 = g_Oh + ((size_t)b * N_ + q0 + wrow + g) * D_ + h * DH_;
    __half* o1 = g_Oh + ((size_t)b * N_ + q0 + wrow + g + 8) * D_ + h * DH_;
#pragma unroll
    for (int nt = 0; nt < 16; nt++) {
        const int col = nt * 8 + 2 * tig;
        *(__half2*)(o0 + col) = __floats2half2_rn(acc[nt][0] * i0, acc[nt][1] * i0);
        *(__half2*)(o1 + col) = __floats2half2_rn(acc[nt][2] * i1, acc[nt][3] * i1);
    }
}

// ---------------- launch -----------------------------------------------------
extern "C" void kernel_launch(void* const* d_in, const int* in_sizes, int n_in,
                              void* d_out, int out_size)
{
    const float* x    = (const float*)d_in[0];
    const float* c    = (const float*)d_in[1];
    const float* wqkv = (const float*)d_in[2];
    const float* wcq  = (const float*)d_in[3];
    const float* wo   = (const float*)d_in[4];
    const float* bo   = (const float*)d_in[5];
    const float* sc   = (const float*)d_in[6];
    const float* csc  = (const float*)d_in[7];
    float* out = (float*)d_out;

    cudaFuncSetAttribute(gemm_h<0>, cudaFuncAttributeMaxDynamicSharedMemorySize, GEMM_SMEM);
    cudaFuncSetAttribute(gemm_h<2>, cudaFuncAttributeMaxDynamicSharedMemorySize, GEMM_SMEM);
    cudaFuncSetAttribute(attn_h, cudaFuncAttributeMaxDynamicSharedMemorySize, ATT_SMEM);

    __half *hx, *hc, *hwqkv, *hwcq, *hwo, *oh;
    cudaGetSymbolAddress((void**)&hx, g_hx);
    cudaGetSymbolAddress((void**)&hc, g_hc);
    cudaGetSymbolAddress((void**)&hwqkv, g_hwqkv);
    cudaGetSymbolAddress((void**)&hwcq, g_hwcq);
    cudaGetSymbolAddress((void**)&hwo, g_hwo);
    cudaGetSymbolAddress((void**)&oh, g_Oh);

    rope_table_k<<<L_, 64>>>();
    cvt_all<<<2048, 256>>>(x, c, wqkv, wcq, wo);

    // fused self+cross QKV (4-warp CTAs, 64x64 warp tiles)
    gemm_h<0><<<dim3(D3_ / 128, 34), 128, GEMM_SMEM>>>(hx, hc, hwqkv, hwcq, nullptr, nullptr);

    normrope_k<<<(B_ * H_ * L_) / 8, 256>>>(sc, csc);

    // attention: 4 warps, 64 queries, register-resident P
    attn_h<<<dim3(N_ / 64, H_, B_), 128, ATT_SMEM>>>();

    gemm_h<2><<<dim3(D_ / 128, (B_ * N_) / 128), 128, GEMM_SMEM>>>(oh, nullptr, hwo, nullptr, bo, out);
}

// round 14
// speedup vs baseline: 1.8026x; 1.8026x over previous
#include <cuda_runtime.h>
#include <cuda_fp16.h>
#include <cstdint>
#include <math.h>

#define B_  2
#define N_  2048
#define NC_ 128
#define D_  2048
#define H_  16
#define DH_ 128
#define L_  (N_ + NC_)     // 2176
#define D3_ (3 * D_)       // 6144

// ---------------- scratch (device globals; no allocations allowed) ----------
__device__ __half g_Qh[(size_t)B_ * H_ * L_ * DH_];   // fp16: pre-norm, then in-place post-norm/rope
__device__ __half g_Kh[(size_t)B_ * H_ * L_ * DH_];
__device__ __half g_Vt[(size_t)B_ * H_ * DH_ * L_];   // fp16 (b,h,dh,l)
__device__ __half g_Oh[(size_t)B_ * N_ * D_];
__device__ __half g_hx[(size_t)B_ * N_ * D_];
__device__ __half g_hc[(size_t)B_ * NC_ * D_];
__device__ __half g_hwqkv[(size_t)D3_ * D_];
__device__ __half g_hwcq[(size_t)D3_ * D_];
__device__ __half g_hwo[(size_t)D_ * D_];
__device__ float2 g_rope[(size_t)L_ * 64];

__device__ __forceinline__ uint32_t smem_u32(const void* p) {
    uint32_t a;
    asm("{ .reg .u64 t; cvta.to.shared.u64 t, %1; cvt.u32.u64 %0, t; }" : "=r"(a) : "l"(p));
    return a;
}
__device__ __forceinline__ void cp16(uint32_t saddr, const void* gaddr) {
    asm volatile("cp.async.cg.shared.global [%0], [%1], 16;" :: "r"(saddr), "l"(gaddr));
}
#define CP_COMMIT() asm volatile("cp.async.commit_group;" ::: "memory")
#define CP_WAIT1()  asm volatile("cp.async.wait_group 1;" ::: "memory")

__device__ __forceinline__ void mma_f16(float* d, const uint32_t* a, const uint32_t* b) {
    asm volatile(
        "mma.sync.aligned.m16n8k16.row.col.f32.f16.f16.f32 "
        "{%0,%1,%2,%3},{%4,%5,%6,%7},{%8,%9},{%0,%1,%2,%3};"
        : "+f"(d[0]), "+f"(d[1]), "+f"(d[2]), "+f"(d[3])
        : "r"(a[0]), "r"(a[1]), "r"(a[2]), "r"(a[3]), "r"(b[0]), "r"(b[1]));
}
__device__ __forceinline__ void ldmx4(uint32_t* r, uint32_t addr) {
    asm volatile("ldmatrix.sync.aligned.m8n8.x4.shared.b16 {%0,%1,%2,%3}, [%4];"
        : "=r"(r[0]), "=r"(r[1]), "=r"(r[2]), "=r"(r[3]) : "r"(addr));
}
__device__ __forceinline__ uint32_t packh2(float a, float b) {
    __half2 h = __floats2half2_rn(a, b);
    return *(uint32_t*)&h;
}

// ---------------- fused fp32 -> fp16 conversion prepass ----------------------
#define NX8  ((B_ * N_ * D_) / 8)
#define NC8  ((B_ * NC_ * D_) / 8)
#define NW8  ((D3_ * D_) / 8)
#define NO8  ((D_ * D_) / 8)
#define NT8  (NX8 + NC8 + 2 * NW8 + NO8)

__global__ void cvt_all(const float* __restrict__ x, const float* __restrict__ c,
                        const float* __restrict__ wqkv, const float* __restrict__ wcq,
                        const float* __restrict__ wo)
{
    for (int i = blockIdx.x * blockDim.x + threadIdx.x; i < NT8; i += gridDim.x * blockDim.x) {
        const float* src; __half* dst; int j = i;
        if (j < NX8)                { src = x;    dst = g_hx; }
        else if ((j -= NX8) < NC8)  { src = c;    dst = g_hc; }
        else if ((j -= NC8) < NW8)  { src = wqkv; dst = g_hwqkv; }
        else if ((j -= NW8) < NW8)  { src = wcq;  dst = g_hwcq; }
        else { j -= NW8;              src = wo;   dst = g_hwo; }
        float4 a = *(const float4*)(src + (size_t)j * 8);
        float4 b = *(const float4*)(src + (size_t)j * 8 + 4);
        uint4 o;
        o.x = packh2(a.x, a.y); o.y = packh2(a.z, a.w);
        o.z = packh2(b.x, b.y); o.w = packh2(b.z, b.w);
        *(uint4*)(dst + (size_t)j * 8) = o;
    }
}

// ---------------- RoPE table --------------------------------------------------
__global__ void rope_table_k()
{
    const int l = blockIdx.x, i = threadIdx.x;
    const float invf = (float)(1.0 / pow(10000.0, (double)i / 64.0));
    const float ang  = (float)l * invf;
    g_rope[l * 64 + i] = make_float2((float)cos((double)ang), (float)sin((double)ang));
}

// ================= fp16 mma GEMM (cp.async 3-stage, ldmatrix) ===============
// R10 config: 256 threads, 8 warps of 64x32, 2 CTAs/SM.
// MODE 0: fused self+cross QKV. Q/K pre-norm fp16 -> g_Qh/g_Kh; V -> g_Vt.
// MODE 2: out-proj + bias (fp32 out).
#define KSLAB  32
#define APADH  40
#define STG_H  (128 * APADH)
#define GEMM_SMEM (3 * 2 * STG_H * 2)      // 61440

template <int MODE>
__global__ __launch_bounds__(256, 2)
void gemm_h(const __half* __restrict__ A0, const __half* __restrict__ A1,
            const __half* __restrict__ W0, const __half* __restrict__ W1,
            const float* __restrict__ bias, float* __restrict__ out)
{
    constexpr int K = D_;
    constexpr int NS = K / KSLAB;
    extern __shared__ __half smh[];

    const int t = threadIdx.x;
    const int wid = t >> 5, lane = t & 31;
    const int g = lane >> 2, tig = lane & 3;
    const int wm = (wid >> 2) * 64;
    const int wn = (wid & 3) * 32;
    const int n0 = blockIdx.x * 128;

    const bool cross = (MODE == 0) && (blockIdx.y >= 32);
    const int m0 = (MODE == 0) ? (cross ? (blockIdx.y - 32) * 128 : blockIdx.y * 128)
                               : blockIdx.y * 128;
    const __half* A = (MODE == 0) ? (cross ? A1 : A0) : A0;
    const __half* W = (MODE == 0) ? (cross ? W1 : W0) : W0;

    const int a_ro = (lane & 7) + ((lane >> 3) & 1) * 8;
    const int a_co = ((lane >> 4) & 1) * 8;
    const int b_ro = (lane & 7) + ((lane >> 4) & 1) * 8;
    const int b_co = ((lane >> 3) & 1) * 8;

    const int rT = t >> 1;
    const int cT = (t & 1) * 2;
    const __half* aRow = A + (size_t)(m0 + rT) * K + cT * 8;
    const __half* bRow = W + (size_t)(n0 + rT) * K + cT * 8;
    const uint32_t sbase = smem_u32(smh);

    float acc[4][4][4];
#pragma unroll
    for (int mi = 0; mi < 4; mi++)
#pragma unroll
        for (int ni = 0; ni < 4; ni++)
#pragma unroll
            for (int r = 0; r < 4; r++) acc[mi][ni][r] = 0.0f;

    auto issue = [&](int slab) {
        const int s = slab % 3;
        const uint32_t as = sbase + (uint32_t)(s * 2 * STG_H) * 2;
        const uint32_t bs = as + (uint32_t)STG_H * 2;
        const int ko = slab * KSLAB;
        const uint32_t soff = (uint32_t)(rT * APADH + cT * 8) * 2;
        cp16(as + soff,      aRow + ko);
        cp16(as + soff + 16, aRow + ko + 8);
        cp16(bs + soff,      bRow + ko);
        cp16(bs + soff + 16, bRow + ko + 8);
    };

    issue(0); CP_COMMIT();
    issue(1); CP_COMMIT();

    for (int kt = 0; kt < NS; kt++) {
        CP_WAIT1();
        __syncthreads();
        if (kt + 2 < NS) issue(kt + 2);
        CP_COMMIT();

        const uint32_t as_u = sbase + (uint32_t)((kt % 3) * 2 * STG_H) * 2;
        const uint32_t bs_u = as_u + (uint32_t)STG_H * 2;
#pragma unroll
        for (int ks = 0; ks < 2; ks++) {
            const int kb = ks * 16;
            uint32_t bf[4][2];
#pragma unroll
            for (int np = 0; np < 2; np++) {
                uint32_t r[4];
                ldmx4(r, bs_u + (uint32_t)((wn + np * 16 + b_ro) * APADH + kb + b_co) * 2);
                bf[2 * np][0] = r[0]; bf[2 * np][1] = r[1];
                bf[2 * np + 1][0] = r[2]; bf[2 * np + 1][1] = r[3];
            }
#pragma unroll
            for (int mi = 0; mi < 4; mi++) {
                uint32_t af[4];
                ldmx4(af, as_u + (uint32_t)((wm + mi * 16 + a_ro) * APADH + kb + a_co) * 2);
#pragma unroll
                for (int ni = 0; ni < 4; ni++)
                    mma_f16(acc[mi][ni], af, bf[ni]);
            }
        }
    }

    if (MODE == 0) {
        const int part = n0 >> 11;
        const int hh   = (n0 & 2047) >> 7;
#pragma unroll
        for (int mi = 0; mi < 4; mi++) {
#pragma unroll
            for (int hi = 0; hi < 2; hi++) {
                const int m = m0 + wm + mi * 16 + g + hi * 8;
                int b, l;
                if (!cross) { b = m >> 11; l = m & 2047; }
                else        { b = m >> 7;  l = N_ + (m & 127); }
                if (part < 2) {
                    __half* dst = (part == 0) ? g_Qh : g_Kh;
                    __half* rowp = dst + ((size_t)(b * H_ + hh) * L_ + l) * DH_;
#pragma unroll
                    for (int ni = 0; ni < 4; ni++) {
                        const int dh = wn + ni * 8 + 2 * tig;
                        *(__half2*)(rowp + dh) =
                            __floats2half2_rn(acc[mi][ni][hi * 2], acc[mi][ni][hi * 2 + 1]);
                    }
                } else {
                    __half* vb = g_Vt + (size_t)(b * H_ + hh) * DH_ * L_;
#pragma unroll
                    for (int ni = 0; ni < 4; ni++) {
                        const int dh = wn + ni * 8 + 2 * tig;
                        vb[(size_t)dh * L_ + l]       = __float2half(acc[mi][ni][hi * 2]);
                        vb[(size_t)(dh + 1) * L_ + l] = __float2half(acc[mi][ni][hi * 2 + 1]);
                    }
                }
            }
        }
    } else {
#pragma unroll
        for (int mi = 0; mi < 4; mi++) {
#pragma unroll
            for (int hi = 0; hi < 2; hi++) {
                const int m = m0 + wm + mi * 16 + g + hi * 8;
                float* op = out + (size_t)m * D_;
#pragma unroll
                for (int ni = 0; ni < 4; ni++) {
                    const int n = n0 + wn + ni * 8 + 2 * tig;
                    *(float2*)(op + n) = make_float2(acc[mi][ni][hi * 2] + bias[n],
                                                     acc[mi][ni][hi * 2 + 1] + bias[n + 1]);
                }
            }
        }
    }
}

// ---------------- L2-norm + scale + RoPE; in-place on fp16, warp per row -----
// Q additionally folded with log2(e)/sqrt(dh) so attention uses exp2.
__global__ __launch_bounds__(256)
void normrope_k(const float* __restrict__ scale, const float* __restrict__ cscale)
{
    const int wid = threadIdx.x >> 5, lane = threadIdx.x & 31;
    const int rg = blockIdx.x * 8 + wid;
    const int b = rg / (H_ * L_);
    const int rem = rg - b * (H_ * L_);
    const int h = rem / L_;
    const int l = rem - h * L_;

    const size_t rbase = (size_t)rg * DH_;
    const int c0 = lane * 4;
    const float* scp = (l < N_) ? scale : cscale;
    const float4 sc4 = *(const float4*)(scp + h * DH_ + c0);
    const float kmul = 45.25483399593904f;                              // sqrt(2048)
    const float qmul = kmul * 0.08838834764831845f * 1.44269504088896f; // /sqrt(128)*log2(e)

    const int i0 = c0 & 63;
    float cs[4], sn[4];
#pragma unroll
    for (int j = 0; j < 4; j++) {
        float2 rp = g_rope[l * 64 + i0 + j];
        cs[j] = rp.x; sn[j] = rp.y;
    }
    const bool lo = (lane < 16);

#pragma unroll
    for (int which = 0; which < 2; which++) {
        __half* ptr = ((which == 0) ? g_Qh : g_Kh) + rbase;
        const float mul = (which == 0) ? qmul : kmul;

        uint2 in = *(const uint2*)(ptr + c0);
        __half2 h01 = *(__half2*)&in.x;
        __half2 h23 = *(__half2*)&in.y;
        float v[4];
        v[0] = __half2float(h01.x); v[1] = __half2float(h01.y);
        v[2] = __half2float(h23.x); v[3] = __half2float(h23.y);
        float ss = v[0] * v[0] + v[1] * v[1] + v[2] * v[2] + v[3] * v[3];
#pragma unroll
        for (int o = 16; o > 0; o >>= 1) ss += __shfl_xor_sync(0xffffffffu, ss, o);
        const float inv = 1.0f / fmaxf(sqrtf(ss), 1e-12f);

        float w[4];
        w[0] = v[0] * inv * sc4.x; w[1] = v[1] * inv * sc4.y;
        w[2] = v[2] * inv * sc4.z; w[3] = v[3] * inv * sc4.w;
        w[0] *= mul; w[1] *= mul; w[2] *= mul; w[3] *= mul;

        float o[4];
#pragma unroll
        for (int j = 0; j < 4; j++) {
            float p = __shfl_xor_sync(0xffffffffu, w[j], 16);
            o[j] = lo ? (w[j] * cs[j] - p * sn[j]) : (p * sn[j] + w[j] * cs[j]);
        }
        uint2 st; st.x = packh2(o[0], o[1]); st.y = packh2(o[2], o[3]);
        *(uint2*)(ptr + c0) = st;
    }
}

// ---------------- flash attention: 4 warps, 64 q, register-resident P --------
#define SKH  136
#define SVTH 72
#define OFF_K   0
#define OFF_VT  (2 * 64 * SKH)
#define ATT_HALVES (OFF_VT + 2 * 128 * SVTH)
#define ATT_SMEM (ATT_HALVES * 2)        // 71680 B

__global__ __launch_bounds__(128)
void attn_h()
{
    extern __shared__ __half smh[];
    const int qt = blockIdx.x, h = blockIdx.y, b = blockIdx.z;
    const int t = threadIdx.x;
    const int wid = t >> 5, lane = t & 31;
    const int g = lane >> 2, tig = lane & 3;
    const int q0 = qt * 64, wrow = wid * 16;
    const size_t base = (size_t)(b * H_ + h) * L_ * DH_;
    const uint32_t sbase = smem_u32(smh);

    const int a_ro = (lane & 7) + ((lane >> 3) & 1) * 8;
    const int a_co = ((lane >> 4) & 1) * 8;
    const int b_ro = (lane & 7) + ((lane >> 4) & 1) * 8;
    const int b_co = ((lane >> 3) & 1) * 8;

    // ---- stage 64-row Q tile, load fragments
    {
        const __half* gq = g_Qh + base + (size_t)q0 * DH_;
#pragma unroll
        for (int ii = 0; ii < 8; ii++) {
            int idx = ii * 128 + t;
            int r = idx >> 4, c8 = (idx & 15) * 8;
            *(uint4*)(smh + r * SKH + c8) = *(const uint4*)(gq + (size_t)r * DH_ + c8);
        }
    }
    __syncthreads();
    uint32_t qf[8][4];
#pragma unroll
    for (int ks = 0; ks < 8; ks++)
        ldmx4(qf[ks], sbase + (uint32_t)((wrow + a_ro) * SKH + ks * 16 + a_co) * 2);
    __syncthreads();

    const __half* gk = g_Kh + base;
    const __half* gvt = g_Vt + (size_t)(b * H_ + h) * DH_ * L_;

    auto issue = [&](int kt) {
        const int bb = kt & 1;
        const int k0 = kt * 64;
#pragma unroll
        for (int ii = 0; ii < 8; ii++) {
            int idx = ii * 128 + t;
            int r = idx >> 4, c8 = (idx & 15) * 8;
            cp16(sbase + (uint32_t)(OFF_K + bb * 64 * SKH + r * SKH + c8) * 2,
                 gk + (size_t)(k0 + r) * DH_ + c8);
        }
#pragma unroll
        for (int ii = 0; ii < 8; ii++) {
            int idx = ii * 128 + t;
            int dh = idx >> 3, c8 = (idx & 7) * 8;
            cp16(sbase + (uint32_t)(OFF_VT + bb * 128 * SVTH + dh * SVTH + c8) * 2,
                 gvt + (size_t)dh * L_ + k0 + c8);
        }
    };

    float acc[16][4];
#pragma unroll
    for (int nt = 0; nt < 16; nt++)
#pragma unroll
        for (int r = 0; r < 4; r++) acc[nt][r] = 0.0f;
    float m0 = -INFINITY, m1 = -INFINITY, l0 = 0.0f, l1 = 0.0f;

    issue(0); CP_COMMIT();

    constexpr int NT = L_ / 64;   // 34
    for (int kt = 0; kt < NT; kt++) {
        __syncthreads();
        if (kt + 1 < NT) issue(kt + 1);
        CP_COMMIT();
        CP_WAIT1();
        __syncthreads();

        const uint32_t sK_u = sbase + (uint32_t)(OFF_K + (kt & 1) * 64 * SKH) * 2;
        const uint32_t sVt_u = sbase + (uint32_t)(OFF_VT + (kt & 1) * 128 * SVTH) * 2;

        // ---- S = Q K^T   (scores already in log2 domain via Q prescale)
        float sfr[8][4];
#pragma unroll
        for (int nt = 0; nt < 8; nt++)
#pragma unroll
            for (int r = 0; r < 4; r++) sfr[nt][r] = 0.0f;
#pragma unroll
        for (int ks = 0; ks < 8; ks++) {
            const int kb = ks * 16;
            uint32_t kf[8][2];
#pragma unroll
            for (int np = 0; np < 4; np++) {
                uint32_t r[4];
                ldmx4(r, sK_u + (uint32_t)((np * 16 + b_ro) * SKH + kb + b_co) * 2);
                kf[2 * np][0] = r[0]; kf[2 * np][1] = r[1];
                kf[2 * np + 1][0] = r[2]; kf[2 * np + 1][1] = r[3];
            }
#pragma unroll
            for (int nt = 0; nt < 8; nt++)
                mma_f16(sfr[nt], qf[ks], kf[nt]);
        }

        // ---- online softmax (base 2), P packed directly into mma A-fragments
        float mx0 = -INFINITY, mx1 = -INFINITY;
#pragma unroll
        for (int nt = 0; nt < 8; nt++) {
            mx0 = fmaxf(mx0, fmaxf(sfr[nt][0], sfr[nt][1]));
            mx1 = fmaxf(mx1, fmaxf(sfr[nt][2], sfr[nt][3]));
        }
        mx0 = fmaxf(mx0, __shfl_xor_sync(0xffffffffu, mx0, 1));
        mx0 = fmaxf(mx0, __shfl_xor_sync(0xffffffffu, mx0, 2));
        mx1 = fmaxf(mx1, __shfl_xor_sync(0xffffffffu, mx1, 1));
        mx1 = fmaxf(mx1, __shfl_xor_sync(0xffffffffu, mx1, 2));
        const float mn0 = fmaxf(m0, mx0), mn1 = fmaxf(m1, mx1);
        const float r0 = exp2f(m0 - mn0), r1 = exp2f(m1 - mn1);
        m0 = mn0; m1 = mn1;

        uint32_t pf[4][4];
        float s0 = 0.0f, s1 = 0.0f;
#pragma unroll
        for (int ks = 0; ks < 4; ks++) {
            const float p00 = exp2f(sfr[2 * ks][0] - mn0);
            const float p01 = exp2f(sfr[2 * ks][1] - mn0);
            const float p10 = exp2f(sfr[2 * ks][2] - mn1);
            const float p11 = exp2f(sfr[2 * ks][3] - mn1);
            const float q00 = exp2f(sfr[2 * ks + 1][0] - mn0);
            const float q01 = exp2f(sfr[2 * ks + 1][1] - mn0);
            const float q10 = exp2f(sfr[2 * ks + 1][2] - mn1);
            const float q11 = exp2f(sfr[2 * ks + 1][3] - mn1);
            s0 += p00 + p01 + q00 + q01;
            s1 += p10 + p11 + q10 + q11;
            pf[ks][0] = packh2(p00, p01);
            pf[ks][1] = packh2(p10, p11);
            pf[ks][2] = packh2(q00, q01);
            pf[ks][3] = packh2(q10, q11);
        }
        s0 += __shfl_xor_sync(0xffffffffu, s0, 1);
        s0 += __shfl_xor_sync(0xffffffffu, s0, 2);
        s1 += __shfl_xor_sync(0xffffffffu, s1, 1);
        s1 += __shfl_xor_sync(0xffffffffu, s1, 2);
        l0 = l0 * r0 + s0;
        l1 = l1 * r1 + s1;
#pragma unroll
        for (int nt = 0; nt < 16; nt++) {
            acc[nt][0] *= r0; acc[nt][1] *= r0;
            acc[nt][2] *= r1; acc[nt][3] *= r1;
        }

        // ---- PV: acc += P V
#pragma unroll
        for (int ks = 0; ks < 4; ks++) {
            const int kb = ks * 16;
#pragma unroll
            for (int np = 0; np < 8; np++) {
                uint32_t r[4];
                ldmx4(r, sVt_u + (uint32_t)((np * 16 + b_ro) * SVTH + kb + b_co) * 2);
                mma_f16(acc[2 * np], pf[ks], r);
                mma_f16(acc[2 * np + 1], pf[ks], r + 2);
            }
        }
    }

    // ---- epilogue (fp16 out)
    const float i0 = 1.0f / l0, i1 = 1.0f / l1;
    __half* o0 = g_Oh + ((size_t)b * N_ + q0 + wrow + g) * D_ + h * DH_;
    __half* o1 = g_Oh + ((size_t)b * N_ + q0 + wrow + g + 8) * D_ + h * DH_;
#pragma unroll
    for (int nt = 0; nt < 16; nt++) {
        const int col = nt * 8 + 2 * tig;
        *(__half2*)(o0 + col) = __floats2half2_rn(acc[nt][0] * i0, acc[nt][1] * i0);
        *(__half2*)(o1 + col) = __floats2half2_rn(acc[nt][2] * i1, acc[nt][3] * i1);
    }
}

// ---------------- launch -----------------------------------------------------
extern "C" void kernel_launch(void* const* d_in, const int* in_sizes, int n_in,
                              void* d_out, int out_size)
{
    const float* x    = (const float*)d_in[0];
    const float* c    = (const float*)d_in[1];
    const float* wqkv = (const float*)d_in[2];
    const float* wcq  = (const float*)d_in[3];
    const float* wo   = (const float*)d_in[4];
    const float* bo   = (const float*)d_in[5];
    const float* sc   = (const float*)d_in[6];
    const float* csc  = (const float*)d_in[7];
    float* out = (float*)d_out;

    cudaFuncSetAttribute(gemm_h<0>, cudaFuncAttributeMaxDynamicSharedMemorySize, GEMM_SMEM);
    cudaFuncSetAttribute(gemm_h<2>, cudaFuncAttributeMaxDynamicSharedMemorySize, GEMM_SMEM);
    cudaFuncSetAttribute(attn_h, cudaFuncAttributeMaxDynamicSharedMemorySize, ATT_SMEM);

    __half *hx, *hc, *hwqkv, *hwcq, *hwo, *oh;
    cudaGetSymbolAddress((void**)&hx, g_hx);
    cudaGetSymbolAddress((void**)&hc, g_hc);
    cudaGetSymbolAddress((void**)&hwqkv, g_hwqkv);
    cudaGetSymbolAddress((void**)&hwcq, g_hwcq);
    cudaGetSymbolAddress((void**)&hwo, g_hwo);
    cudaGetSymbolAddress((void**)&oh, g_Oh);

    rope_table_k<<<L_, 64>>>();
    cvt_all<<<4096, 256>>>(x, c, wqkv, wcq, wo);

    // fused self+cross QKV (8-warp CTAs, 64x32 warp tiles — R10 config)
    gemm_h<0><<<dim3(D3_ / 128, 34), 256, GEMM_SMEM>>>(hx, hc, hwqkv, hwcq, nullptr, nullptr);

    normrope_k<<<(B_ * H_ * L_) / 8, 256>>>(sc, csc);

    // attention: 4 warps, 64 queries, register-resident P
    attn_h<<<dim3(N_ / 64, H_, B_), 128, ATT_SMEM>>>();

    gemm_h<2><<<dim3(D_ / 128, (B_ * N_) / 128), 256, GEMM_SMEM>>>(oh, nullptr, hwo, nullptr, bo, out);
}